// round 13
// baseline (speedup 1.0000x reference)
#include <cuda_runtime.h>
#include <cstdint>

#define Bq    4
#define Nq    2048
#define DINq  256
#define DOUTq 256
#define Hq    4
#define HDq   64
#define NEG_SLOPE 0.2f

#define JSPLIT 2
#define NJH    (Nq / JSPLIT)       // 1024 j per split
#define NCH    (NJH / 32)          // 32 chunks per block

// ---------------- scratch (no allocation allowed) ----------------
__device__ float g_h[Bq * Nq * DOUTq];             // 8 MB
__device__ float g_ssrc[Bq * Nq * Hq];
__device__ float g_sdst[Bq * Nq * Hq];
__device__ float g_part[JSPLIT][Bq * Nq * DOUTq];  // 16 MB partial sums
__device__ float g_lpart[JSPLIT][Bq * Nq * Hq];    // partial denominators

// ---------------- packed f32x2 helpers (gemm) ----------------
__device__ __forceinline__ void ffma2(unsigned long long& acc,
                                      unsigned long long p,
                                      unsigned long long h) {
    asm("fma.rn.f32x2 %0, %1, %2, %0;" : "+l"(acc) : "l"(p), "l"(h));
}
__device__ __forceinline__ unsigned long long pack2(float lo, float hi) {
    unsigned long long r;
    asm("mov.b64 %0, {%1, %2};" : "=l"(r) : "f"(lo), "f"(hi));
    return r;
}
__device__ __forceinline__ void unpack2(unsigned long long v, float& lo, float& hi) {
    asm("mov.b64 {%0, %1}, %2;" : "=f"(lo), "=f"(hi) : "l"(v));
}

// ---------------- tf32 mma helpers ----------------
__device__ __forceinline__ uint32_t f2tf32(float f) {
    uint32_t r;
    asm("cvt.rna.tf32.f32 %0, %1;" : "=r"(r) : "f"(f));
    return r;
}
__device__ __forceinline__ void mma_tf32(float* d, const uint32_t* a, const uint32_t* b) {
    asm volatile(
        "mma.sync.aligned.m16n8k8.row.col.f32.tf32.tf32.f32 "
        "{%0,%1,%2,%3}, {%4,%5,%6,%7}, {%8,%9}, {%0,%1,%2,%3};"
        : "+f"(d[0]), "+f"(d[1]), "+f"(d[2]), "+f"(d[3])
        : "r"(a[0]), "r"(a[1]), "r"(a[2]), "r"(a[3]), "r"(b[0]), "r"(b[1]));
}

// =====================================================================
// Kernel 1: h = x @ W^T.  128x64 tile, 256 threads, 8x4 micro-tile.
// =====================================================================
__global__ __launch_bounds__(256) void gemm_xWT_kernel(const float* __restrict__ x,
                                                       const float* __restrict__ W) {
    __shared__ float as[16][132];
    __shared__ float bs[16][68];

    const int tid = threadIdx.x;
    const int tx = tid & 15;
    const int ty = tid >> 4;
    const int row0 = blockIdx.x * 128;
    const int col0 = blockIdx.y * 64;

    unsigned long long acc2[4][4];
#pragma unroll
    for (int i = 0; i < 4; i++)
#pragma unroll
        for (int j = 0; j < 4; j++) acc2[i][j] = 0ull;

    const int arow = tid >> 1;
    const int aq   = (tid & 1) * 8;
    const int brow = tid >> 2;
    const int bq   = (tid & 3) * 4;
    const float* xp = x + (size_t)(row0 + arow) * DINq + aq;
    const float* wp = W + (size_t)(col0 + brow) * DINq + bq;

    for (int kc = 0; kc < DINq; kc += 16) {
        float4 v0 = *(const float4*)(xp + kc);
        float4 v1 = *(const float4*)(xp + kc + 4);
        float4 wv = *(const float4*)(wp + kc);
        as[aq + 0][arow] = v0.x; as[aq + 1][arow] = v0.y;
        as[aq + 2][arow] = v0.z; as[aq + 3][arow] = v0.w;
        as[aq + 4][arow] = v1.x; as[aq + 5][arow] = v1.y;
        as[aq + 6][arow] = v1.z; as[aq + 7][arow] = v1.w;
        bs[bq + 0][brow] = wv.x; bs[bq + 1][brow] = wv.y;
        bs[bq + 2][brow] = wv.z; bs[bq + 3][brow] = wv.w;
        __syncthreads();

#pragma unroll
        for (int k = 0; k < 16; k++) {
            float a8[8], b4[4];
            *(float4*)a8       = *(const float4*)&as[k][ty * 8];
            *(float4*)(a8 + 4) = *(const float4*)&as[k][ty * 8 + 4];
            *(float4*)b4       = *(const float4*)&bs[k][tx * 4];
            unsigned long long bp[4];
#pragma unroll
            for (int j = 0; j < 4; j++) bp[j] = pack2(b4[j], b4[j]);
#pragma unroll
            for (int i = 0; i < 4; i++) {
                unsigned long long ap = pack2(a8[2 * i], a8[2 * i + 1]);
#pragma unroll
                for (int j = 0; j < 4; j++) ffma2(acc2[i][j], ap, bp[j]);
            }
        }
        __syncthreads();
    }

#pragma unroll
    for (int i = 0; i < 4; i++) {
        float lo[4], hi[4];
#pragma unroll
        for (int j = 0; j < 4; j++) unpack2(acc2[i][j], lo[j], hi[j]);
        float4 o0; o0.x = lo[0]; o0.y = lo[1]; o0.z = lo[2]; o0.w = lo[3];
        float4 o1; o1.x = hi[0]; o1.y = hi[1]; o1.z = hi[2]; o1.w = hi[3];
        const int r = row0 + ty * 8 + 2 * i;
        *(float4*)&g_h[(size_t)(r + 0) * DOUTq + col0 + tx * 4] = o0;
        *(float4*)&g_h[(size_t)(r + 1) * DOUTq + col0 + tx * 4] = o1;
    }
}

// =====================================================================
// Kernel 2: per-(row,head) scores via warp dot products
// =====================================================================
__global__ __launch_bounds__(256) void score_kernel(const float* __restrict__ a_src,
                                                    const float* __restrict__ a_dst) {
    const int task = blockIdx.x * 8 + (threadIdx.x >> 5);   // row*4 + head
    const int ln = threadIdx.x & 31;
    const int row = task >> 2;
    const int head = task & 3;

    const float* hp = g_h + (size_t)row * DOUTq + head * HDq;
    float v0 = hp[ln], v1 = hp[ln + 32];
    float s1 = v0 * a_src[head * HDq + ln] + v1 * a_src[head * HDq + ln + 32];
    float s2 = v0 * a_dst[head * HDq + ln] + v1 * a_dst[head * HDq + ln + 32];
#pragma unroll
    for (int off = 16; off > 0; off >>= 1) {
        s1 += __shfl_xor_sync(0xFFFFFFFFu, s1, off);
        s2 += __shfl_xor_sync(0xFFFFFFFFu, s2, off);
    }
    if (ln == 0) {
        g_ssrc[task] = s1;
        g_sdst[task] = s2;
    }
}

// =====================================================================
// Kernel 3: tensor-core aggregation (tf32 mma), j-split partials.
// Grid (N/32, B, JSPLIT); block z accumulates j in [z*1024, z*1024+1024).
// Writes unnormalized partial D + partial softmax denominator.
// Same per-chunk schedule as the 166us kernel (P-phase -> pre-barrier
// B prefetch -> adj/sdst prefetch -> barrier -> mma).
// =====================================================================
__global__ __launch_bounds__(256, 3) void agg_mma_kernel(const float* __restrict__ adj) {
    __shared__ uint32_t sP[2][Hq][32][36];   // tf32 alpha, double buffered
    __shared__ float sS[32][4];

    const int t = threadIdx.x;
    const int w = t >> 5;
    const int lane = t & 31;
    const int head = w & 3;
    const int nh = w >> 2;
    const int g = lane >> 2;
    const int ct = lane & 3;
    const int b = blockIdx.y;
    const int z = blockIdx.z;
    const int i0 = blockIdx.x * 32;
    const int bN = b * Nq;
    const int jbase = z * NJH;

    if (t < 32)
        *(float4*)&sS[t][0] = *(const float4*)&g_ssrc[(size_t)(bN + i0 + t) * 4];
    __syncthreads();

    float d[2][4][4];
    float dones[2][4];
#pragma unroll
    for (int s = 0; s < 2; s++) {
#pragma unroll
        for (int nt = 0; nt < 4; nt++)
#pragma unroll
            for (int q = 0; q < 4; q++) d[s][nt][q] = 0.f;
#pragma unroll
        for (int q = 0; q < 4; q++) dones[s][q] = 0.f;
    }

    uint32_t bones[2];
    bones[0] = bones[1] = (g == 0) ? __float_as_uint(1.0f) : 0u;

    const float* hcolbase = g_h + (size_t)(bN + jbase) * DOUTq + head * HDq + nh * 32;
    const float* adjbase = adj + (size_t)(bN + i0 + w * 4) * Nq + jbase;

    // prologue: chunk 0 adj/sdst
    float av[4];
    float4 sd4;
    sd4 = __ldg((const float4*)&g_sdst[(size_t)(bN + jbase + lane) * 4]);
#pragma unroll
    for (int r = 0; r < 4; r++)
        av[r] = __ldg(adjbase + (size_t)r * Nq + lane);

    for (int c = 0; c < NCH; c++) {
        const int j0 = c * 32;                    // relative to jbase
        const int buf = c & 1;

        // ---------- P-phase ----------
#pragma unroll
        for (int r = 0; r < 4; r++) {
            const int row = w * 4 + r;
            float avr = av[r];
            float4 ss = *(const float4*)&sS[row][0];
            float e0 = ss.x + sd4.x; e0 = fmaxf(e0, NEG_SLOPE * e0);
            float e1 = ss.y + sd4.y; e1 = fmaxf(e1, NEG_SLOPE * e1);
            float e2 = ss.z + sd4.z; e2 = fmaxf(e2, NEG_SLOPE * e2);
            float e3 = ss.w + sd4.w; e3 = fmaxf(e3, NEG_SLOPE * e3);
            sP[buf][0][row][lane] = f2tf32(avr * __expf(e0));
            sP[buf][1][row][lane] = f2tf32(avr * __expf(e1));
            sP[buf][2][row][lane] = f2tf32(avr * __expf(e2));
            sP[buf][3][row][lane] = f2tf32(avr * __expf(e3));
        }

        // ---------- B prefetch for THIS chunk (pre-barrier, MLP=32) ----------
        float braw[4][4][2];
        {
            const float* hc = hcolbase + (size_t)j0 * DOUTq;
#pragma unroll
            for (int kk = 0; kk < 4; kk++) {
                const float* hb = hc + (size_t)(kk * 8 + ct) * DOUTq + g;
#pragma unroll
                for (int nt = 0; nt < 4; nt++) {
                    braw[kk][nt][0] = __ldg(hb + nt * 8);
                    braw[kk][nt][1] = __ldg(hb + 4 * DOUTq + nt * 8);
                }
            }
        }

        // ---------- prefetch next chunk's adj/sdst ----------
        if (c + 1 < NCH) {
            const int j1 = j0 + 32;
            sd4 = __ldg((const float4*)&g_sdst[(size_t)(bN + jbase + j1 + lane) * 4]);
#pragma unroll
            for (int r = 0; r < 4; r++)
                av[r] = __ldg(adjbase + (size_t)r * Nq + j1 + lane);
        }
        __syncthreads();

        // ---------- mma-phase ----------
#pragma unroll
        for (int kk = 0; kk < 4; kk++) {
            uint32_t bf[4][2];
#pragma unroll
            for (int nt = 0; nt < 4; nt++) {
                bf[nt][0] = f2tf32(braw[kk][nt][0]);
                bf[nt][1] = f2tf32(braw[kk][nt][1]);
            }
#pragma unroll
            for (int s = 0; s < 2; s++) {
                const int ar = s * 16 + g;
                const int acl = kk * 8 + ct;
                uint32_t af[4];
                af[0] = sP[buf][head][ar][acl];
                af[1] = sP[buf][head][ar + 8][acl];
                af[2] = sP[buf][head][ar][acl + 4];
                af[3] = sP[buf][head][ar + 8][acl + 4];
#pragma unroll
                for (int nt = 0; nt < 4; nt++) mma_tf32(d[s][nt], af, bf[nt]);
                mma_tf32(dones[s], af, bones);
            }
        }
    }

    // ---------- epilogue: store unnormalized partials ----------
    float* pout = g_part[z];
#pragma unroll
    for (int s = 0; s < 2; s++) {
        const int rowA = i0 + s * 16 + g;
        const int rowB = rowA + 8;
        const int col = head * HDq + nh * 32 + 2 * ct;
#pragma unroll
        for (int nt = 0; nt < 4; nt++) {
            float2 oA; oA.x = d[s][nt][0]; oA.y = d[s][nt][1];
            float2 oB; oB.x = d[s][nt][2]; oB.y = d[s][nt][3];
            *(float2*)&pout[(size_t)(bN + rowA) * DOUTq + col + nt * 8] = oA;
            *(float2*)&pout[(size_t)(bN + rowB) * DOUTq + col + nt * 8] = oB;
        }
        // partial denominators: col 0 of ones-mma lives in ct==0 lanes
        if (nh == 0 && ct == 0) {
            g_lpart[z][(size_t)(bN + rowA) * 4 + head] = dones[s][0];
            g_lpart[z][(size_t)(bN + rowB) * 4 + head] = dones[s][2];
        }
    }
}

// =====================================================================
// Kernel 4: combine partials:  out = (p0 + p1) / (l0 + l1)
// One float4 per thread.
// =====================================================================
__global__ __launch_bounds__(256) void combine_kernel(float* __restrict__ out) {
    const int idx = blockIdx.x * 256 + threadIdx.x;       // float4 index
    const int row = idx >> 6;                             // global row (b*N+i)
    const int c4 = idx & 63;
    const int head = c4 >> 4;

    float l = g_lpart[0][(size_t)row * 4 + head] + g_lpart[1][(size_t)row * 4 + head];
    float li = 1.0f / l;

    const float4 p0 = *(const float4*)&g_part[0][(size_t)idx * 4];
    const float4 p1 = *(const float4*)&g_part[1][(size_t)idx * 4];
    float4 o;
    o.x = (p0.x + p1.x) * li;
    o.y = (p0.y + p1.y) * li;
    o.z = (p0.z + p1.z) * li;
    o.w = (p0.w + p1.w) * li;
    *(float4*)&out[(size_t)idx * 4] = o;
}

// =====================================================================
extern "C" void kernel_launch(void* const* d_in, const int* in_sizes, int n_in,
                              void* d_out, int out_size) {
    const float* x     = (const float*)d_in[0];   // [B,N,DIN]
    const float* adj   = (const float*)d_in[1];   // [B,N,N]
    const float* W     = (const float*)d_in[2];   // [DOUT,DIN]
    const float* a_src = (const float*)d_in[3];   // [H,HD]
    const float* a_dst = (const float*)d_in[4];   // [H,HD]
    float* out = (float*)d_out;                   // [B,N,DOUT]

    gemm_xWT_kernel<<<dim3((Bq * Nq) / 128, DOUTq / 64), 256>>>(x, W);
    score_kernel<<<(Bq * Nq * Hq) / 8, 256>>>(a_src, a_dst);
    agg_mma_kernel<<<dim3(Nq / 32, Bq, JSPLIT), 256>>>(adj);
    combine_kernel<<<(Bq * Nq * DOUTq / 4) / 256, 256>>>(out);
}

// round 15
// speedup vs baseline: 1.7387x; 1.7387x over previous
#include <cuda_runtime.h>
#include <cstdint>

#define Bq    4
#define Nq    2048
#define DINq  256
#define DOUTq 256
#define Hq    4
#define HDq   64
#define NEG_SLOPE 0.2f

#define NC    (Nq / 32)

// smem layout (words)
#define SH_STRIDE 264                       // 264 mod 32 = 8 -> conflict-free frag reads
#define SH_WORDS  (2 * 32 * SH_STRIDE)      // 16896 (double-buffered h tile)
#define SP_WORDS  (Hq * 32 * 36)            // 4608  (single-buffered alpha)
#define SS_WORDS  (32 * 4)
#define SMEM_BYTES ((SH_WORDS + SP_WORDS + SS_WORDS) * 4)   // 86.7 KB

// ---------------- scratch (no allocation allowed) ----------------
__device__ float g_h[Bq * Nq * DOUTq];       // 8 MB: h = x @ W^T
__device__ float g_ssrc[Bq * Nq * Hq];
__device__ float g_sdst[Bq * Nq * Hq];

// ---------------- packed f32x2 helpers (gemm) ----------------
__device__ __forceinline__ void ffma2(unsigned long long& acc,
                                      unsigned long long p,
                                      unsigned long long h) {
    asm("fma.rn.f32x2 %0, %1, %2, %0;" : "+l"(acc) : "l"(p), "l"(h));
}
__device__ __forceinline__ unsigned long long pack2(float lo, float hi) {
    unsigned long long r;
    asm("mov.b64 %0, {%1, %2};" : "=l"(r) : "f"(lo), "f"(hi));
    return r;
}
__device__ __forceinline__ void unpack2(unsigned long long v, float& lo, float& hi) {
    asm("mov.b64 {%0, %1}, %2;" : "=f"(lo), "=f"(hi) : "l"(v));
}

// ---------------- tf32 mma helpers ----------------
__device__ __forceinline__ uint32_t f2tf32(float f) {
    uint32_t r;
    asm("cvt.rna.tf32.f32 %0, %1;" : "=r"(r) : "f"(f));
    return r;
}
__device__ __forceinline__ void mma_tf32(float* d, const uint32_t* a, const uint32_t* b) {
    asm volatile(
        "mma.sync.aligned.m16n8k8.row.col.f32.tf32.tf32.f32 "
        "{%0,%1,%2,%3}, {%4,%5,%6,%7}, {%8,%9}, {%0,%1,%2,%3};"
        : "+f"(d[0]), "+f"(d[1]), "+f"(d[2]), "+f"(d[3])
        : "r"(a[0]), "r"(a[1]), "r"(a[2]), "r"(a[3]), "r"(b[0]), "r"(b[1]));
}

// ---------------- cp.async helpers ----------------
__device__ __forceinline__ void cp_async16(uint32_t dst_smem, const float* src) {
    asm volatile("cp.async.cg.shared.global [%0], [%1], 16;" :: "r"(dst_smem), "l"(src));
}
#define CP_COMMIT() asm volatile("cp.async.commit_group;")
#define CP_WAIT1()  asm volatile("cp.async.wait_group 1;" ::: "memory")
#define CP_WAIT0()  asm volatile("cp.async.wait_group 0;" ::: "memory")

// =====================================================================
// Kernel 1: h = x @ W^T.  128x64 tile, 256 threads, 8x4 micro-tile.
// =====================================================================
__global__ __launch_bounds__(256) void gemm_xWT_kernel(const float* __restrict__ x,
                                                       const float* __restrict__ W) {
    __shared__ float as[16][132];
    __shared__ float bs[16][68];

    const int tid = threadIdx.x;
    const int tx = tid & 15;
    const int ty = tid >> 4;
    const int row0 = blockIdx.x * 128;
    const int col0 = blockIdx.y * 64;

    unsigned long long acc2[4][4];
#pragma unroll
    for (int i = 0; i < 4; i++)
#pragma unroll
        for (int j = 0; j < 4; j++) acc2[i][j] = 0ull;

    const int arow = tid >> 1;
    const int aq   = (tid & 1) * 8;
    const int brow = tid >> 2;
    const int bq   = (tid & 3) * 4;
    const float* xp = x + (size_t)(row0 + arow) * DINq + aq;
    const float* wp = W + (size_t)(col0 + brow) * DINq + bq;

    for (int kc = 0; kc < DINq; kc += 16) {
        float4 v0 = *(const float4*)(xp + kc);
        float4 v1 = *(const float4*)(xp + kc + 4);
        float4 wv = *(const float4*)(wp + kc);
        as[aq + 0][arow] = v0.x; as[aq + 1][arow] = v0.y;
        as[aq + 2][arow] = v0.z; as[aq + 3][arow] = v0.w;
        as[aq + 4][arow] = v1.x; as[aq + 5][arow] = v1.y;
        as[aq + 6][arow] = v1.z; as[aq + 7][arow] = v1.w;
        bs[bq + 0][brow] = wv.x; bs[bq + 1][brow] = wv.y;
        bs[bq + 2][brow] = wv.z; bs[bq + 3][brow] = wv.w;
        __syncthreads();

#pragma unroll
        for (int k = 0; k < 16; k++) {
            float a8[8], b4[4];
            *(float4*)a8       = *(const float4*)&as[k][ty * 8];
            *(float4*)(a8 + 4) = *(const float4*)&as[k][ty * 8 + 4];
            *(float4*)b4       = *(const float4*)&bs[k][tx * 4];
            unsigned long long bp[4];
#pragma unroll
            for (int j = 0; j < 4; j++) bp[j] = pack2(b4[j], b4[j]);
#pragma unroll
            for (int i = 0; i < 4; i++) {
                unsigned long long ap = pack2(a8[2 * i], a8[2 * i + 1]);
#pragma unroll
                for (int j = 0; j < 4; j++) ffma2(acc2[i][j], ap, bp[j]);
            }
        }
        __syncthreads();
    }

#pragma unroll
    for (int i = 0; i < 4; i++) {
        float lo[4], hi[4];
#pragma unroll
        for (int j = 0; j < 4; j++) unpack2(acc2[i][j], lo[j], hi[j]);
        float4 o0; o0.x = lo[0]; o0.y = lo[1]; o0.z = lo[2]; o0.w = lo[3];
        float4 o1; o1.x = hi[0]; o1.y = hi[1]; o1.z = hi[2]; o1.w = hi[3];
        const int r = row0 + ty * 8 + 2 * i;
        *(float4*)&g_h[(size_t)(r + 0) * DOUTq + col0 + tx * 4] = o0;
        *(float4*)&g_h[(size_t)(r + 1) * DOUTq + col0 + tx * 4] = o1;
    }
}

// =====================================================================
// Kernel 2: per-(row,head) scores via warp dot products
// =====================================================================
__global__ __launch_bounds__(256) void score_kernel(const float* __restrict__ a_src,
                                                    const float* __restrict__ a_dst) {
    const int task = blockIdx.x * 8 + (threadIdx.x >> 5);   // row*4 + head
    const int ln = threadIdx.x & 31;
    const int row = task >> 2;
    const int head = task & 3;

    const float* hp = g_h + (size_t)row * DOUTq + head * HDq;
    float v0 = hp[ln], v1 = hp[ln + 32];
    float s1 = v0 * a_src[head * HDq + ln] + v1 * a_src[head * HDq + ln + 32];
    float s2 = v0 * a_dst[head * HDq + ln] + v1 * a_dst[head * HDq + ln + 32];
#pragma unroll
    for (int off = 16; off > 0; off >>= 1) {
        s1 += __shfl_xor_sync(0xFFFFFFFFu, s1, off);
        s2 += __shfl_xor_sync(0xFFFFFFFFu, s2, off);
    }
    if (ln == 0) {
        g_ssrc[task] = s1;
        g_sdst[task] = s2;
    }
}

// =====================================================================
// Kernel 3: tensor-core aggregation (tf32 mma) + ones-mma softmax denom.
// Block = 256 thr / 8 warps, i-tile = 32, grid (N/32, B).
// h tile (32 x 256) staged via cp.async into DOUBLE-buffered sH;
// alpha in SINGLE-buffered sP (2 barriers/chunk). B frags become
// conflict-free LDS.32 (bank = 8*ct + g). 86.7 KB smem -> 2 CTAs/SM.
// =====================================================================
__global__ __launch_bounds__(256, 2) void agg_mma_kernel(const float* __restrict__ adj,
                                                         float* __restrict__ out) {
    extern __shared__ float smem[];
    float*    sH = smem;                                   // [2][32][264]
    uint32_t* sP = (uint32_t*)(smem + SH_WORDS);           // [4][32][36]
    float*    sS = smem + SH_WORDS + SP_WORDS;             // [32][4]

    const int t = threadIdx.x;
    const int w = t >> 5;
    const int lane = t & 31;
    const int head = w & 3;
    const int nh = w >> 2;
    const int g = lane >> 2;
    const int ct = lane & 3;
    const int b = blockIdx.y;
    const int i0 = blockIdx.x * 32;
    const int bN = b * Nq;
    const int colbase = head * HDq + nh * 32;

    if (t < 32)
        *(float4*)&sS[t * 4] = *(const float4*)&g_ssrc[(size_t)(bN + i0 + t) * 4];

    // staging geometry: 8 threads x 16B per row
    const int srow = t >> 3;
    const int sseg = (t & 7) * 4;
    const uint32_t sh_u32 = (uint32_t)__cvta_generic_to_shared(sH);
    const float* hstage_src = g_h + (size_t)(bN + srow) * DOUTq + sseg;

    float d[2][4][4];
    float dones[2][4];
#pragma unroll
    for (int s = 0; s < 2; s++) {
#pragma unroll
        for (int nt = 0; nt < 4; nt++)
#pragma unroll
            for (int q = 0; q < 4; q++) d[s][nt][q] = 0.f;
#pragma unroll
        for (int q = 0; q < 4; q++) dones[s][q] = 0.f;
    }
    uint32_t bones[2];
    bones[0] = bones[1] = (g == 0) ? __float_as_uint(1.0f) : 0u;

    const float* adjbase = adj + (size_t)(bN + i0 + w * 4) * Nq;

    // prologue: chunk 0 adj/sdst regs + stage chunk 0 into sH buf 0
    float av[4];
    float4 sd4;
    sd4 = __ldg((const float4*)&g_sdst[(size_t)(bN + lane) * 4]);
#pragma unroll
    for (int r = 0; r < 4; r++)
        av[r] = __ldg(adjbase + (size_t)r * Nq + lane);

    {
        uint32_t dst = sh_u32 + (uint32_t)(srow * SH_STRIDE + sseg) * 4;
#pragma unroll
        for (int q = 0; q < 8; q++)
            cp_async16(dst + q * 32 * 4, hstage_src + q * 32);
        CP_COMMIT();
    }
    __syncthreads();   // sS visible

    for (int c = 0; c < NC; c++) {
        const int j0 = c * 32;
        const int buf = c & 1;

        // ---------- P-phase: rows w*4..w*4+3, all 4 heads -> single-buf sP ----
#pragma unroll
        for (int r = 0; r < 4; r++) {
            const int row = w * 4 + r;
            float avr = av[r];
            float4 ss = *(const float4*)&sS[row * 4];
            float e0 = ss.x + sd4.x; e0 = fmaxf(e0, NEG_SLOPE * e0);
            float e1 = ss.y + sd4.y; e1 = fmaxf(e1, NEG_SLOPE * e1);
            float e2 = ss.z + sd4.z; e2 = fmaxf(e2, NEG_SLOPE * e2);
            float e3 = ss.w + sd4.w; e3 = fmaxf(e3, NEG_SLOPE * e3);
            sP[0 * 1152 + row * 36 + lane] = f2tf32(avr * __expf(e0));
            sP[1 * 1152 + row * 36 + lane] = f2tf32(avr * __expf(e1));
            sP[2 * 1152 + row * 36 + lane] = f2tf32(avr * __expf(e2));
            sP[3 * 1152 + row * 36 + lane] = f2tf32(avr * __expf(e3));
        }

        // ---------- stage NEXT chunk's h tile into the other sH buffer ------
        if (c + 1 < NC) {
            const int nbuf = (c + 1) & 1;
            uint32_t dst = sh_u32 + (uint32_t)(nbuf * (32 * SH_STRIDE) + srow * SH_STRIDE + sseg) * 4;
            const float* src = hstage_src + (size_t)(j0 + 32) * DOUTq;
#pragma unroll
            for (int q = 0; q < 8; q++)
                cp_async16(dst + q * 32 * 4, src + q * 32);
            CP_COMMIT();
        }

        // ---------- prefetch next chunk's adj/sdst into registers -----------
        if (c + 1 < NC) {
            const int j1 = j0 + 32;
            sd4 = __ldg((const float4*)&g_sdst[(size_t)(bN + j1 + lane) * 4]);
#pragma unroll
            for (int r = 0; r < 4; r++)
                av[r] = __ldg(adjbase + (size_t)r * Nq + j1 + lane);
        }

        // ---------- ensure THIS chunk's h stage landed, then barrier --------
        if (c + 1 < NC) { CP_WAIT1(); } else { CP_WAIT0(); }
        __syncthreads();                       // sP ready + sH[buf] visible

        // ---------- mma-phase: A from sP, B from sH[buf] (LDS, no conflicts) -
        const float* sHb = sH + buf * (32 * SH_STRIDE) + colbase + g;
        const uint32_t* sPh = sP + head * 1152;
#pragma unroll
        for (int kk = 0; kk < 4; kk++) {
            const int r0 = kk * 8 + ct;
            uint32_t bf[4][2];
#pragma unroll
            for (int nt = 0; nt < 4; nt++) {
                bf[nt][0] = f2tf32(sHb[r0 * SH_STRIDE + nt * 8]);
                bf[nt][1] = f2tf32(sHb[(r0 + 4) * SH_STRIDE + nt * 8]);
            }
            const int acl = kk * 8 + ct;
#pragma unroll
            for (int s = 0; s < 2; s++) {
                const int ar = s * 16 + g;
                uint32_t af[4];
                af[0] = sPh[ar * 36 + acl];
                af[1] = sPh[(ar + 8) * 36 + acl];
                af[2] = sPh[ar * 36 + acl + 4];
                af[3] = sPh[(ar + 8) * 36 + acl + 4];
#pragma unroll
                for (int nt = 0; nt < 4; nt++) mma_tf32(d[s][nt], af, bf[nt]);
                mma_tf32(dones[s], af, bones);
            }
        }
        __syncthreads();                       // all mma reads of sP done
    }

    // ---------- epilogue: normalize and store ----------
#pragma unroll
    for (int s = 0; s < 2; s++) {
        float lA = __shfl_sync(0xFFFFFFFFu, dones[s][0], lane & ~3);
        float lB = __shfl_sync(0xFFFFFFFFu, dones[s][2], lane & ~3);
        float liA = 1.0f / lA;
        float liB = 1.0f / lB;
        const int rowA = i0 + s * 16 + g;
        const int rowB = rowA + 8;
        const int col = colbase + 2 * ct;
#pragma unroll
        for (int nt = 0; nt < 4; nt++) {
            float2 oA; oA.x = d[s][nt][0] * liA; oA.y = d[s][nt][1] * liA;
            float2 oB; oB.x = d[s][nt][2] * liB; oB.y = d[s][nt][3] * liB;
            *(float2*)&out[(size_t)(bN + rowA) * DOUTq + col + nt * 8] = oA;
            *(float2*)&out[(size_t)(bN + rowB) * DOUTq + col + nt * 8] = oB;
        }
    }
}

// =====================================================================
extern "C" void kernel_launch(void* const* d_in, const int* in_sizes, int n_in,
                              void* d_out, int out_size) {
    const float* x     = (const float*)d_in[0];   // [B,N,DIN]
    const float* adj   = (const float*)d_in[1];   // [B,N,N]
    const float* W     = (const float*)d_in[2];   // [DOUT,DIN]
    const float* a_src = (const float*)d_in[3];   // [H,HD]
    const float* a_dst = (const float*)d_in[4];   // [H,HD]
    float* out = (float*)d_out;                   // [B,N,DOUT]

    cudaFuncSetAttribute(agg_mma_kernel,
                         cudaFuncAttributeMaxDynamicSharedMemorySize, SMEM_BYTES);

    gemm_xWT_kernel<<<dim3((Bq * Nq) / 128, DOUTq / 64), 256>>>(x, W);
    score_kernel<<<(Bq * Nq * Hq) / 8, 256>>>(a_src, a_dst);
    agg_mma_kernel<<<dim3(Nq / 32, Bq), 256, SMEM_BYTES>>>(adj, out);
}

// round 17
// speedup vs baseline: 1.9325x; 1.1115x over previous
#include <cuda_runtime.h>
#include <cstdint>

#define Bq    4
#define Nq    2048
#define DINq  256
#define DOUTq 256
#define Hq    4
#define HDq   64
#define NEG_SLOPE 0.2f

#define NC    (Nq / 32)

// ---- agg smem layout (words) ----
#define SH_STRIDE 264
#define SH_WORDS  (2 * 32 * SH_STRIDE)
#define SP_WORDS  (Hq * 32 * 36)
#define SS_WORDS  (32 * 4)
#define SMEM_BYTES ((SH_WORDS + SP_WORDS + SS_WORDS) * 4)   // 86.7 KB

// ---- gemm smem layout (words): x[2][128][36], W[2][64][36] ----
#define GX_WORDS (128 * 36)
#define GW_WORDS (64 * 36)
#define GSMEM_BYTES ((2 * GX_WORDS + 2 * GW_WORDS) * 4)     // 55.3 KB

// ---------------- scratch (no allocation allowed) ----------------
__device__ float g_h[Bq * Nq * DOUTq];       // 8 MB: h = x @ W^T
__device__ float g_ssrc[Bq * Nq * Hq];
__device__ float g_sdst[Bq * Nq * Hq];

// ---------------- tf32 mma helpers ----------------
__device__ __forceinline__ uint32_t f2tf32(float f) {
    uint32_t r;
    asm("cvt.rna.tf32.f32 %0, %1;" : "=r"(r) : "f"(f));
    return r;
}
__device__ __forceinline__ void mma_tf32(float* d, const uint32_t* a, const uint32_t* b) {
    asm volatile(
        "mma.sync.aligned.m16n8k8.row.col.f32.tf32.tf32.f32 "
        "{%0,%1,%2,%3}, {%4,%5,%6,%7}, {%8,%9}, {%0,%1,%2,%3};"
        : "+f"(d[0]), "+f"(d[1]), "+f"(d[2]), "+f"(d[3])
        : "r"(a[0]), "r"(a[1]), "r"(a[2]), "r"(a[3]), "r"(b[0]), "r"(b[1]));
}

// ---------------- cp.async helpers ----------------
__device__ __forceinline__ void cp_async16(uint32_t dst_smem, const float* src) {
    asm volatile("cp.async.cg.shared.global [%0], [%1], 16;" :: "r"(dst_smem), "l"(src));
}
#define CP_COMMIT() asm volatile("cp.async.commit_group;")
#define CP_WAIT1()  asm volatile("cp.async.wait_group 1;" ::: "memory")
#define CP_WAIT0()  asm volatile("cp.async.wait_group 0;" ::: "memory")

// =====================================================================
// Kernel 1: h = x @ W^T via tf32 mma.  Tile M=128, N=64; 8 warps, each
// 32x32.  K chunked by 32, cp.async double-buffered, stride-36 smem
// (bank = 4g+ct: conflict-free fragment reads).
// =====================================================================
__global__ __launch_bounds__(256) void gemm_mma_kernel(const float* __restrict__ x,
                                                       const float* __restrict__ W) {
    extern __shared__ float gsm[];
    float* sX = gsm;                         // [2][128][36]
    float* sW = gsm + 2 * GX_WORDS;          // [2][64][36]

    const int t = threadIdx.x;
    const int w = t >> 5;
    const int lane = t & 31;
    const int mq = w & 3;                    // m-quad: rows mq*32..+31
    const int nq = w >> 2;                   // n-half: cols nq*32..+31
    const int g = lane >> 2;
    const int ct = lane & 3;
    const int row0 = blockIdx.x * 128;
    const int col0 = blockIdx.y * 64;

    const uint32_t sx_u32 = (uint32_t)__cvta_generic_to_shared(sX);
    const uint32_t sw_u32 = (uint32_t)__cvta_generic_to_shared(sW);

    // staging: x -> 2 thr/row (16 floats each); W -> 4 thr/row (8 floats)
    const int xrow = t >> 1, xoff = (t & 1) * 16;
    const int wrow = t >> 2, woff = (t & 3) * 8;
    const float* xsrc = x + (size_t)(row0 + xrow) * DINq + xoff;
    const float* wsrc = W + (size_t)(col0 + wrow) * DINq + woff;

    float d[2][4][4];
#pragma unroll
    for (int s = 0; s < 2; s++)
#pragma unroll
        for (int nt = 0; nt < 4; nt++)
#pragma unroll
            for (int q = 0; q < 4; q++) d[s][nt][q] = 0.f;

    // prologue: stage chunk 0
    {
        uint32_t xd = sx_u32 + (uint32_t)(xrow * 36 + xoff) * 4;
#pragma unroll
        for (int q = 0; q < 4; q++) cp_async16(xd + q * 16, xsrc + q * 4);
        uint32_t wd = sw_u32 + (uint32_t)(wrow * 36 + woff) * 4;
#pragma unroll
        for (int q = 0; q < 2; q++) cp_async16(wd + q * 16, wsrc + q * 4);
        CP_COMMIT();
    }

    for (int c = 0; c < DINq / 32; c++) {
        const int buf = c & 1;

        // stage next chunk into other buffer
        if (c + 1 < DINq / 32) {
            const int nbuf = (c + 1) & 1;
            const int kc = (c + 1) * 32;
            uint32_t xd = sx_u32 + (uint32_t)(nbuf * GX_WORDS + xrow * 36 + xoff) * 4;
#pragma unroll
            for (int q = 0; q < 4; q++) cp_async16(xd + q * 16, xsrc + kc + q * 4);
            uint32_t wd = sw_u32 + (uint32_t)(nbuf * GW_WORDS + wrow * 36 + woff) * 4;
#pragma unroll
            for (int q = 0; q < 2; q++) cp_async16(wd + q * 16, wsrc + kc + q * 4);
            CP_COMMIT();
        }

        if (c + 1 < DINq / 32) { CP_WAIT1(); } else { CP_WAIT0(); }
        __syncthreads();

        const float* sXb = sX + buf * GX_WORDS + (mq * 32) * 36;
        const float* sWb = sW + buf * GW_WORDS + (nq * 32) * 36;
#pragma unroll
        for (int kk = 0; kk < 4; kk++) {
            const int k0 = kk * 8;
            uint32_t bf[4][2];
#pragma unroll
            for (int nt = 0; nt < 4; nt++) {
                bf[nt][0] = f2tf32(sWb[(nt * 8 + g) * 36 + k0 + ct]);
                bf[nt][1] = f2tf32(sWb[(nt * 8 + g) * 36 + k0 + ct + 4]);
            }
#pragma unroll
            for (int s = 0; s < 2; s++) {
                const int ar = s * 16 + g;
                uint32_t af[4];
                af[0] = f2tf32(sXb[ar * 36 + k0 + ct]);
                af[1] = f2tf32(sXb[(ar + 8) * 36 + k0 + ct]);
                af[2] = f2tf32(sXb[ar * 36 + k0 + ct + 4]);
                af[3] = f2tf32(sXb[(ar + 8) * 36 + k0 + ct + 4]);
#pragma unroll
                for (int nt = 0; nt < 4; nt++) mma_tf32(d[s][nt], af, bf[nt]);
            }
        }
        __syncthreads();   // all reads done before next stage overwrites
    }

    // epilogue
#pragma unroll
    for (int s = 0; s < 2; s++) {
        const int rowA = row0 + mq * 32 + s * 16 + g;
        const int rowB = rowA + 8;
        const int col = col0 + nq * 32 + 2 * ct;
#pragma unroll
        for (int nt = 0; nt < 4; nt++) {
            float2 oA; oA.x = d[s][nt][0]; oA.y = d[s][nt][1];
            float2 oB; oB.x = d[s][nt][2]; oB.y = d[s][nt][3];
            *(float2*)&g_h[(size_t)rowA * DOUTq + col + nt * 8] = oA;
            *(float2*)&g_h[(size_t)rowB * DOUTq + col + nt * 8] = oB;
        }
    }
}

// =====================================================================
// Kernel 2: per-(row,head) scores via warp dot products
// =====================================================================
__global__ __launch_bounds__(256) void score_kernel(const float* __restrict__ a_src,
                                                    const float* __restrict__ a_dst) {
    const int task = blockIdx.x * 8 + (threadIdx.x >> 5);   // row*4 + head
    const int ln = threadIdx.x & 31;
    const int row = task >> 2;
    const int head = task & 3;

    const float* hp = g_h + (size_t)row * DOUTq + head * HDq;
    float v0 = hp[ln], v1 = hp[ln + 32];
    float s1 = v0 * a_src[head * HDq + ln] + v1 * a_src[head * HDq + ln + 32];
    float s2 = v0 * a_dst[head * HDq + ln] + v1 * a_dst[head * HDq + ln + 32];
#pragma unroll
    for (int off = 16; off > 0; off >>= 1) {
        s1 += __shfl_xor_sync(0xFFFFFFFFu, s1, off);
        s2 += __shfl_xor_sync(0xFFFFFFFFu, s2, off);
    }
    if (ln == 0) {
        g_ssrc[task] = s1;
        g_sdst[task] = s2;
    }
}

// =====================================================================
// Kernel 3: tensor-core aggregation (tf32 mma) + ones-mma softmax denom.
// (R15 structure, unchanged: cp.async double-buffered sH, single sP,
//  2 barriers/chunk, 86.7 KB smem -> 2 CTAs/SM.)
// =====================================================================
__global__ __launch_bounds__(256, 2) void agg_mma_kernel(const float* __restrict__ adj,
                                                         float* __restrict__ out) {
    extern __shared__ float smem[];
    float*    sH = smem;                                   // [2][32][264]
    uint32_t* sP = (uint32_t*)(smem + SH_WORDS);           // [4][32][36]
    float*    sS = smem + SH_WORDS + SP_WORDS;             // [32][4]

    const int t = threadIdx.x;
    const int w = t >> 5;
    const int lane = t & 31;
    const int head = w & 3;
    const int nh = w >> 2;
    const int g = lane >> 2;
    const int ct = lane & 3;
    const int b = blockIdx.y;
    const int i0 = blockIdx.x * 32;
    const int bN = b * Nq;
    const int colbase = head * HDq + nh * 32;

    if (t < 32)
        *(float4*)&sS[t * 4] = *(const float4*)&g_ssrc[(size_t)(bN + i0 + t) * 4];

    const int srow = t >> 3;
    const int sseg = (t & 7) * 4;
    const uint32_t sh_u32 = (uint32_t)__cvta_generic_to_shared(sH);
    const float* hstage_src = g_h + (size_t)(bN + srow) * DOUTq + sseg;

    float d[2][4][4];
    float dones[2][4];
#pragma unroll
    for (int s = 0; s < 2; s++) {
#pragma unroll
        for (int nt = 0; nt < 4; nt++)
#pragma unroll
            for (int q = 0; q < 4; q++) d[s][nt][q] = 0.f;
#pragma unroll
        for (int q = 0; q < 4; q++) dones[s][q] = 0.f;
    }
    uint32_t bones[2];
    bones[0] = bones[1] = (g == 0) ? __float_as_uint(1.0f) : 0u;

    const float* adjbase = adj + (size_t)(bN + i0 + w * 4) * Nq;

    float av[4];
    float4 sd4;
    sd4 = __ldg((const float4*)&g_sdst[(size_t)(bN + lane) * 4]);
#pragma unroll
    for (int r = 0; r < 4; r++)
        av[r] = __ldg(adjbase + (size_t)r * Nq + lane);

    {
        uint32_t dst = sh_u32 + (uint32_t)(srow * SH_STRIDE + sseg) * 4;
#pragma unroll
        for (int q = 0; q < 8; q++)
            cp_async16(dst + q * 32 * 4, hstage_src + q * 32);
        CP_COMMIT();
    }
    __syncthreads();

    for (int c = 0; c < NC; c++) {
        const int j0 = c * 32;
        const int buf = c & 1;

#pragma unroll
        for (int r = 0; r < 4; r++) {
            const int row = w * 4 + r;
            float avr = av[r];
            float4 ss = *(const float4*)&sS[row * 4];
            float e0 = ss.x + sd4.x; e0 = fmaxf(e0, NEG_SLOPE * e0);
            float e1 = ss.y + sd4.y; e1 = fmaxf(e1, NEG_SLOPE * e1);
            float e2 = ss.z + sd4.z; e2 = fmaxf(e2, NEG_SLOPE * e2);
            float e3 = ss.w + sd4.w; e3 = fmaxf(e3, NEG_SLOPE * e3);
            sP[0 * 1152 + row * 36 + lane] = f2tf32(avr * __expf(e0));
            sP[1 * 1152 + row * 36 + lane] = f2tf32(avr * __expf(e1));
            sP[2 * 1152 + row * 36 + lane] = f2tf32(avr * __expf(e2));
            sP[3 * 1152 + row * 36 + lane] = f2tf32(avr * __expf(e3));
        }

        if (c + 1 < NC) {
            const int nbuf = (c + 1) & 1;
            uint32_t dst = sh_u32 + (uint32_t)(nbuf * (32 * SH_STRIDE) + srow * SH_STRIDE + sseg) * 4;
            const float* src = hstage_src + (size_t)(j0 + 32) * DOUTq;
#pragma unroll
            for (int q = 0; q < 8; q++)
                cp_async16(dst + q * 32 * 4, src + q * 32);
            CP_COMMIT();
        }

        if (c + 1 < NC) {
            const int j1 = j0 + 32;
            sd4 = __ldg((const float4*)&g_sdst[(size_t)(bN + j1 + lane) * 4]);
#pragma unroll
            for (int r = 0; r < 4; r++)
                av[r] = __ldg(adjbase + (size_t)r * Nq + j1 + lane);
        }

        if (c + 1 < NC) { CP_WAIT1(); } else { CP_WAIT0(); }
        __syncthreads();

        const float* sHb = sH + buf * (32 * SH_STRIDE) + colbase + g;
        const uint32_t* sPh = sP + head * 1152;
#pragma unroll
        for (int kk = 0; kk < 4; kk++) {
            const int r0 = kk * 8 + ct;
            uint32_t bf[4][2];
#pragma unroll
            for (int nt = 0; nt < 4; nt++) {
                bf[nt][0] = f2tf32(sHb[r0 * SH_STRIDE + nt * 8]);
                bf[nt][1] = f2tf32(sHb[(r0 + 4) * SH_STRIDE + nt * 8]);
            }
            const int acl = kk * 8 + ct;
#pragma unroll
            for (int s = 0; s < 2; s++) {
                const int ar = s * 16 + g;
                uint32_t af[4];
                af[0] = sPh[ar * 36 + acl];
                af[1] = sPh[(ar + 8) * 36 + acl];
                af[2] = sPh[ar * 36 + acl + 4];
                af[3] = sPh[(ar + 8) * 36 + acl + 4];
#pragma unroll
                for (int nt = 0; nt < 4; nt++) mma_tf32(d[s][nt], af, bf[nt]);
                mma_tf32(dones[s], af, bones);
            }
        }
        __syncthreads();
    }

#pragma unroll
    for (int s = 0; s < 2; s++) {
        float lA = __shfl_sync(0xFFFFFFFFu, dones[s][0], lane & ~3);
        float lB = __shfl_sync(0xFFFFFFFFu, dones[s][2], lane & ~3);
        float liA = 1.0f / lA;
        float liB = 1.0f / lB;
        const int rowA = i0 + s * 16 + g;
        const int rowB = rowA + 8;
        const int col = colbase + 2 * ct;
#pragma unroll
        for (int nt = 0; nt < 4; nt++) {
            float2 oA; oA.x = d[s][nt][0] * liA; oA.y = d[s][nt][1] * liA;
            float2 oB; oB.x = d[s][nt][2] * liB; oB.y = d[s][nt][3] * liB;
            *(float2*)&out[(size_t)(bN + rowA) * DOUTq + col + nt * 8] = oA;
            *(float2*)&out[(size_t)(bN + rowB) * DOUTq + col + nt * 8] = oB;
        }
    }
}

// =====================================================================
extern "C" void kernel_launch(void* const* d_in, const int* in_sizes, int n_in,
                              void* d_out, int out_size) {
    const float* x     = (const float*)d_in[0];   // [B,N,DIN]
    const float* adj   = (const float*)d_in[1];   // [B,N,N]
    const float* W     = (const float*)d_in[2];   // [DOUT,DIN]
    const float* a_src = (const float*)d_in[3];   // [H,HD]
    const float* a_dst = (const float*)d_in[4];   // [H,HD]
    float* out = (float*)d_out;                   // [B,N,DOUT]

    cudaFuncSetAttribute(gemm_mma_kernel,
                         cudaFuncAttributeMaxDynamicSharedMemorySize, GSMEM_BYTES);
    cudaFuncSetAttribute(agg_mma_kernel,
                         cudaFuncAttributeMaxDynamicSharedMemorySize, SMEM_BYTES);

    gemm_mma_kernel<<<dim3((Bq * Nq) / 128, DOUTq / 64), 256, GSMEM_BYTES>>>(x, W);
    score_kernel<<<(Bq * Nq * Hq) / 8, 256>>>(a_src, a_dst);
    agg_mma_kernel<<<dim3(Nq / 32, Bq), 256, SMEM_BYTES>>>(adj, out);
}